// round 15
// baseline (speedup 1.0000x reference)
#include <cuda_runtime.h>
#include <cuda_bf16.h>

#define B_  4
#define L_  2048
#define D_  1024
#define H_  16
#define HD_ 64
#define M_  (B_*L_)
#define EPS 1e-5f
// 0.125 * log2(e), folded into Q projection output
#define QSCALE 0.1803368801111244f

typedef unsigned uint;

// Scratch (device globals; 16B aligned)
__device__ __align__(16) __nv_bfloat16 g_xb[(size_t)M_*D_];
__device__ __align__(16) __nv_bfloat16 g_WbT[4][(size_t)D_*D_];   // W^T: [n][k]
__device__ __align__(16) __nv_bfloat16 g_Qb[(size_t)B_*H_*L_*HD_];
__device__ __align__(16) __nv_bfloat16 g_Kb[(size_t)B_*H_*L_*HD_];
__device__ __align__(16) __nv_bfloat16 g_Vb[(size_t)B_*H_*L_*HD_];
__device__ __align__(16) __nv_bfloat16 g_ctxb[(size_t)M_*D_];
__device__ __align__(16) float g_Y[(size_t)M_*D_];

// ---------------------------------------------------------------------------
// PTX helpers
// ---------------------------------------------------------------------------
__device__ __forceinline__ uint smem_u32(const void* p) {
    return (uint)__cvta_generic_to_shared(p);
}
__device__ __forceinline__ void cpasync16(uint dst, const void* src) {
    asm volatile("cp.async.cg.shared.global [%0], [%1], 16;\n" :: "r"(dst), "l"(src));
}
__device__ __forceinline__ void cp_commit() { asm volatile("cp.async.commit_group;\n"); }
template<int N> __device__ __forceinline__ void cp_wait() {
    asm volatile("cp.async.wait_group %0;\n" :: "n"(N));
}
__device__ __forceinline__ uint packbf2(float lo, float hi) {
    uint r;
    asm("cvt.rn.bf16x2.f32 %0, %1, %2;" : "=r"(r) : "f"(hi), "f"(lo));
    return r;
}
__device__ __forceinline__ float ex2f(float x) {
    float r;
    asm("ex2.approx.f32 %0, %1;" : "=f"(r) : "f"(x));
    return r;
}
__device__ __forceinline__ void ldm4(uint& r0, uint& r1, uint& r2, uint& r3, uint a) {
    asm volatile("ldmatrix.sync.aligned.m8n8.x4.shared.b16 {%0,%1,%2,%3}, [%4];"
                 : "=r"(r0), "=r"(r1), "=r"(r2), "=r"(r3) : "r"(a));
}
__device__ __forceinline__ void ldm4t(uint& r0, uint& r1, uint& r2, uint& r3, uint a) {
    asm volatile("ldmatrix.sync.aligned.m8n8.x4.trans.shared.b16 {%0,%1,%2,%3}, [%4];"
                 : "=r"(r0), "=r"(r1), "=r"(r2), "=r"(r3) : "r"(a));
}
__device__ __forceinline__ void mma16(float* c, const uint* a, uint b0, uint b1) {
    asm volatile(
        "mma.sync.aligned.m16n8k16.row.col.f32.bf16.bf16.f32 "
        "{%0,%1,%2,%3}, {%4,%5,%6,%7}, {%8,%9}, {%0,%1,%2,%3};\n"
        : "+f"(c[0]), "+f"(c[1]), "+f"(c[2]), "+f"(c[3])
        : "r"(a[0]), "r"(a[1]), "r"(a[2]), "r"(a[3]), "r"(b0), "r"(b1));
}

// ---------------------------------------------------------------------------
// Merged conversion kernel: blocks [0,4096) convert x; [4096,8192) transpose W.
// ---------------------------------------------------------------------------
__global__ void __launch_bounds__(256)
cvt_all_kernel(const float* __restrict__ x,
               const float* __restrict__ Wq, const float* __restrict__ Wk,
               const float* __restrict__ Wv, const float* __restrict__ Wo) {
    int b = blockIdx.x;
    if (b < 4096) {
        int i = b * 256 + threadIdx.x;
        const float4* sp = reinterpret_cast<const float4*>(x) + (size_t)i * 2;
        float4 a = sp[0], c = sp[1];
        uint4 o;
        o.x = packbf2(a.x, a.y); o.y = packbf2(a.z, a.w);
        o.z = packbf2(c.x, c.y); o.w = packbf2(c.z, c.w);
        reinterpret_cast<uint4*>(g_xb)[i] = o;
    } else {
        __shared__ float t[32][33];
        int wb = b - 4096;
        int z = wb >> 10;
        int tile = wb & 1023;
        int k0 = (tile & 31) * 32, n0 = (tile >> 5) * 32;
        const float* src = (z == 0) ? Wq : (z == 1) ? Wk : (z == 2) ? Wv : Wo;
        int tx = threadIdx.x & 31, ty = threadIdx.x >> 5;
#pragma unroll
        for (int i = 0; i < 4; i++)
            t[ty + 8 * i][tx] = src[(size_t)(k0 + ty + 8 * i) * D_ + n0 + tx];
        __syncthreads();
        __nv_bfloat16* dst = g_WbT[z];
#pragma unroll
        for (int i = 0; i < 4; i++)
            dst[(size_t)(n0 + ty + 8 * i) * D_ + k0 + tx] =
                __float2bfloat16(t[tx][ty + 8 * i]);
    }
}

// ---------------------------------------------------------------------------
// GEMM core: CTA tile 128x128, warp tile 64x64 (4 warps 2x2), BK=64,
// 3-stage cp.async (16 iterations), 128 threads, 2 CTAs/SM.
// mma:ldm4 ratio 4:1 (matches the measured-efficient attention shape).
// ---------------------------------------------------------------------------
#define GKR 72
#define G_ASTG (128*GKR*2)          // 18432 B
#define G_BSTG (128*GKR*2)          // 18432 B
#define G_STG  (G_ASTG + G_BSTG)    // 36864 B
#define G_SMEM (3*G_STG)            // 110592 B

__device__ __forceinline__ void g_issue(const __nv_bfloat16* __restrict__ A,
                                        const __nv_bfloat16* __restrict__ Bt,
                                        int bm, int bn, int k0, uint sbase) {
    int tid = threadIdx.x;
#pragma unroll
    for (int i = 0; i < 8; i++) {                 // A: 1024 chunks / 128 thr
        int c = tid + i * 128;
        int r = c >> 3, kc = (c & 7) * 8;
        cpasync16(sbase + (uint)(r * GKR + kc) * 2,
                  A + (size_t)(bm + r) * D_ + k0 + kc);
    }
#pragma unroll
    for (int i = 0; i < 8; i++) {                 // B: 1024 chunks
        int c = tid + i * 128;
        int r = c >> 3, kc = (c & 7) * 8;
        cpasync16(sbase + G_ASTG + (uint)(r * GKR + kc) * 2,
                  Bt + (size_t)(bn + r) * D_ + k0 + kc);
    }
}

__device__ __forceinline__ void g_compute(uint sA, uint sB, int lane,
                                          int wm, int wn, float acc[4][8][4]) {
    int ra = lane & 15;
    int ca0 = (lane & 16) ? 8 : 0;
    int rb = (lane & 7) + ((lane & 16) ? 8 : 0);
#pragma unroll
    for (int ks = 0; ks < 4; ks++) {
        uint a[4][4];
#pragma unroll
        for (int mt = 0; mt < 4; mt++) {
            int r = wm * 64 + mt * 16 + ra;
            ldm4(a[mt][0], a[mt][1], a[mt][2], a[mt][3],
                 sA + (uint)(r * GKR + ks * 16 + ca0) * 2);
        }
        int cb = ks * 16 + ((lane & 8) ? 8 : 0);
#pragma unroll
        for (int np = 0; np < 4; np++) {
            int n = wn * 64 + np * 16 + rb;
            uint b0, b1, b2, b3;
            ldm4(b0, b1, b2, b3, sB + (uint)(n * GKR + cb) * 2);
#pragma unroll
            for (int mt = 0; mt < 4; mt++) {
                mma16(acc[mt][np * 2],     a[mt], b0, b1);
                mma16(acc[mt][np * 2 + 1], a[mt], b2, b3);
            }
        }
    }
}

__device__ __forceinline__ void g_main(const __nv_bfloat16* __restrict__ A,
                                       const __nv_bfloat16* __restrict__ Bt,
                                       int bm, int bn, float acc[4][8][4]) {
    extern __shared__ __align__(16) __nv_bfloat16 dsm[];
    uint sb = smem_u32(dsm);
    int lane = threadIdx.x & 31, w = threadIdx.x >> 5;   // w in 0..3
    int wm = w & 1, wn = w >> 1;

    g_issue(A, Bt, bm, bn, 0, sb);
    cp_commit();
    g_issue(A, Bt, bm, bn, 64, sb + G_STG);
    cp_commit();

    for (int it = 0; it < 16; it++) {
        if (it + 1 < 16) cp_wait<1>(); else cp_wait<0>();
        __syncthreads();
        uint base = sb + (uint)(it % 3) * G_STG;
        g_compute(base, base + G_ASTG, lane, wm, wn, acc);
        if (it + 2 < 16) {
            uint nbase = sb + (uint)((it + 2) % 3) * G_STG;
            g_issue(A, Bt, bm, bn, (it + 2) * 64, nbase);
            cp_commit();
        }
    }
}

// ---------------------------------------------------------------------------
// Kernel 1: QKV projection -> bf16 [B,H,L,HD]; grid (8, 64, 3), 128 threads
// ---------------------------------------------------------------------------
__global__ void __launch_bounds__(128, 2)
qkv_kernel(const float* __restrict__ bq, const float* __restrict__ bk,
           const float* __restrict__ bv) {
    int z = blockIdx.z;
    int bm = blockIdx.y * 128, bn = blockIdx.x * 128;
    const float* bias = (z == 0) ? bq : (z == 1) ? bk : bv;
    __nv_bfloat16* out = (z == 0) ? g_Qb : (z == 1) ? g_Kb : g_Vb;
    const float scale = (z == 0) ? QSCALE : 1.0f;

    float acc[4][8][4];
#pragma unroll
    for (int mt = 0; mt < 4; mt++)
#pragma unroll
        for (int nt = 0; nt < 8; nt++)
#pragma unroll
            for (int j = 0; j < 4; j++) acc[mt][nt][j] = 0.f;

    g_main(g_xb, g_WbT[z], bm, bn, acc);

    int lane = threadIdx.x & 31, w = threadIdx.x >> 5;
    int wm = w & 1, wn = w >> 1;
#pragma unroll
    for (int mt = 0; mt < 4; mt++) {
        int r0 = bm + wm * 64 + mt * 16 + (lane >> 2);
#pragma unroll
        for (int nt = 0; nt < 8; nt++) {
            int c0 = bn + wn * 64 + nt * 8 + 2 * (lane & 3);
            int h = c0 >> 6, d = c0 & 63;
            float bx = bias[c0], by = bias[c0 + 1];
#pragma unroll
            for (int rr = 0; rr < 2; rr++) {
                int r = r0 + rr * 8;
                int bb = r >> 11, ll = r & (L_ - 1);
                uint p = packbf2((acc[mt][nt][rr * 2]     + bx) * scale,
                                 (acc[mt][nt][rr * 2 + 1] + by) * scale);
                *reinterpret_cast<uint*>(
                    &out[(((size_t)(bb * H_ + h)) * L_ + ll) * HD_ + d]) = p;
            }
        }
    }
}

// ---------------------------------------------------------------------------
// Kernel 3: output projection + bias + residual -> g_Y fp32; grid (8, 64)
// ---------------------------------------------------------------------------
__global__ void __launch_bounds__(128, 2)
oproj_kernel(const float* __restrict__ bo, const float* __restrict__ x) {
    int bm = blockIdx.y * 128, bn = blockIdx.x * 128;

    float acc[4][8][4];
#pragma unroll
    for (int mt = 0; mt < 4; mt++)
#pragma unroll
        for (int nt = 0; nt < 8; nt++)
#pragma unroll
            for (int j = 0; j < 4; j++) acc[mt][nt][j] = 0.f;

    g_main(g_ctxb, g_WbT[3], bm, bn, acc);

    int lane = threadIdx.x & 31, w = threadIdx.x >> 5;
    int wm = w & 1, wn = w >> 1;
#pragma unroll
    for (int mt = 0; mt < 4; mt++) {
        int r0 = bm + wm * 64 + mt * 16 + (lane >> 2);
#pragma unroll
        for (int nt = 0; nt < 8; nt++) {
            int c0 = bn + wn * 64 + nt * 8 + 2 * (lane & 3);
            float bx = bo[c0], by = bo[c0 + 1];
#pragma unroll
            for (int rr = 0; rr < 2; rr++) {
                int r = r0 + rr * 8;
                const float2 xr = *reinterpret_cast<const float2*>(&x[(size_t)r * D_ + c0]);
                float2 v;
                v.x = acc[mt][nt][rr * 2]     + bx + xr.x;
                v.y = acc[mt][nt][rr * 2 + 1] + by + xr.y;
                *reinterpret_cast<float2*>(&g_Y[(size_t)r * D_ + c0]) = v;
            }
        }
    }
}

// ---------------------------------------------------------------------------
// Kernel 2: Flash attention (R14 form — measured best). 128 threads, 4 warps,
// 128-q tile, each warp 32 q-rows (K/V fragments shared across 2 m-tiles).
// ---------------------------------------------------------------------------
#define QST 72
#define KVSTG (2 * 64 * QST)     // halves per stage

__device__ __forceinline__ void attn_issue_kv(const __nv_bfloat16* __restrict__ Kp,
                                              const __nv_bfloat16* __restrict__ Vp,
                                              int t, uint kb, uint vb, int tid) {
#pragma unroll
    for (int i = 0; i < 4; i++) {
        int idx = tid + i * 128;
        int r = idx >> 3, c = (idx & 7) * 8;
        size_t g = (size_t)(t * 64 + r) * HD_ + c;
        cpasync16(kb + (uint)(r * QST + c) * 2, Kp + g);
        cpasync16(vb + (uint)(r * QST + c) * 2, Vp + g);
    }
}

__global__ void __launch_bounds__(128, 2)
attn_kernel() {
    __shared__ __align__(16) __nv_bfloat16 KV[2][KVSTG];   // 36864 B

    int tid = threadIdx.x, lane = tid & 31, w = tid >> 5;   // w in 0..3
    int qt = blockIdx.x, bh = blockIdx.y;
    const __nv_bfloat16* Qp = g_Qb + (size_t)bh * L_ * HD_ + (size_t)qt * 128 * HD_;
    const __nv_bfloat16* Kp = g_Kb + (size_t)bh * L_ * HD_;
    const __nv_bfloat16* Vp = g_Vb + (size_t)bh * L_ * HD_;

    uint kb[2] = { smem_u32(&KV[0][0]), smem_u32(&KV[1][0]) };
    uint vb[2] = { kb[0] + 64 * QST * 2, kb[1] + 64 * QST * 2 };
    uint qb = kb[0];

    // Stage Q (128 x 64, stride QST) into stage-0
#pragma unroll
    for (int i = 0; i < 8; i++) {
        int idx = tid + i * 128;
        int r = idx >> 3, c = (idx & 7) * 8;
        cpasync16(qb + (uint)(r * QST + c) * 2, Qp + (size_t)r * HD_ + c);
    }
    cp_commit();
    cp_wait<0>();
    __syncthreads();

    // Preload Q fragments: 2 m-tiles x 4 k-steps
    uint qf[2][4][4];
    {
        int koff = (lane >> 4) ? 8 : 0;
#pragma unroll
        for (int mt = 0; mt < 2; mt++) {
            int m = w * 32 + mt * 16 + (lane & 15);
#pragma unroll
            for (int ks = 0; ks < 4; ks++)
                ldm4(qf[mt][ks][0], qf[mt][ks][1], qf[mt][ks][2], qf[mt][ks][3],
                     qb + (uint)(m * QST + ks * 16 + koff) * 2);
        }
    }
    __syncthreads();

    attn_issue_kv(Kp, Vp, 0, kb[0], vb[0], tid);
    cp_commit();
    attn_issue_kv(Kp, Vp, 1, kb[1], vb[1], tid);
    cp_commit();

    float o[2][8][4];
#pragma unroll
    for (int mt = 0; mt < 2; mt++)
#pragma unroll
        for (int nt = 0; nt < 8; nt++)
#pragma unroll
            for (int j = 0; j < 4; j++) o[mt][nt][j] = 0.f;
    float lsum[2][2] = {{0.f, 0.f}, {0.f, 0.f}};

    int row = lane & 7, grp = lane >> 3;

    for (int t = 0; t < L_ / 64; t++) {
        if (t + 2 < L_ / 64) cp_wait<1>(); else cp_wait<0>();
        __syncthreads();
        uint kcur = kb[t & 1], vcur = vb[t & 1];

        // ---- S = Q @ K^T : K fragments shared across both m-tiles ----
        float s[2][8][4];
#pragma unroll
        for (int mt = 0; mt < 2; mt++)
#pragma unroll
            for (int nt = 0; nt < 8; nt++)
#pragma unroll
                for (int j = 0; j < 4; j++) s[mt][nt][j] = 0.f;
#pragma unroll
        for (int ks = 0; ks < 4; ks++) {
            int kk = ks * 16 + ((grp & 1) ? 8 : 0);
#pragma unroll
            for (int np = 0; np < 4; np++) {
                int nn = np * 16 + ((grp >= 2) ? 8 : 0) + row;
                uint b0, b1, b2, b3;
                ldm4(b0, b1, b2, b3, kcur + (uint)(nn * QST + kk) * 2);
#pragma unroll
                for (int mt = 0; mt < 2; mt++) {
                    mma16(s[mt][np * 2],     qf[mt][ks], b0, b1);
                    mma16(s[mt][np * 2 + 1], qf[mt][ks], b2, b3);
                }
            }
        }

        // ---- P = 2^S; partial row sums ----
#pragma unroll
        for (int mt = 0; mt < 2; mt++)
#pragma unroll
            for (int nt = 0; nt < 8; nt++) {
                s[mt][nt][0] = ex2f(s[mt][nt][0]);
                s[mt][nt][1] = ex2f(s[mt][nt][1]);
                s[mt][nt][2] = ex2f(s[mt][nt][2]);
                s[mt][nt][3] = ex2f(s[mt][nt][3]);
                lsum[mt][0] += s[mt][nt][0] + s[mt][nt][1];
                lsum[mt][1] += s[mt][nt][2] + s[mt][nt][3];
            }

        // ---- O += P @ V : V fragments shared across both m-tiles ----
#pragma unroll
        for (int kt = 0; kt < 4; kt++) {
            uint a[2][4];
#pragma unroll
            for (int mt = 0; mt < 2; mt++) {
                a[mt][0] = packbf2(s[mt][2 * kt][0],     s[mt][2 * kt][1]);
                a[mt][1] = packbf2(s[mt][2 * kt][2],     s[mt][2 * kt][3]);
                a[mt][2] = packbf2(s[mt][2 * kt + 1][0], s[mt][2 * kt + 1][1]);
                a[mt][3] = packbf2(s[mt][2 * kt + 1][2], s[mt][2 * kt + 1][3]);
            }
            int kk = kt * 16 + ((grp & 1) ? 8 : 0) + row;
#pragma unroll
            for (int np = 0; np < 4; np++) {
                int nn = np * 16 + ((grp >= 2) ? 8 : 0);
                uint b0, b1, b2, b3;
                ldm4t(b0, b1, b2, b3, vcur + (uint)(kk * QST + nn) * 2);
#pragma unroll
                for (int mt = 0; mt < 2; mt++) {
                    mma16(o[mt][np * 2],     a[mt], b0, b1);
                    mma16(o[mt][np * 2 + 1], a[mt], b2, b3);
                }
            }
        }
        __syncthreads();
        if (t + 2 < L_ / 64) {
            attn_issue_kv(Kp, Vp, t + 2, kb[t & 1], vb[t & 1], tid);
            cp_commit();
        }
    }

    // Row-sum reduction across the 4-lane row groups
#pragma unroll
    for (int mt = 0; mt < 2; mt++) {
        lsum[mt][0] += __shfl_xor_sync(0xffffffffu, lsum[mt][0], 1);
        lsum[mt][0] += __shfl_xor_sync(0xffffffffu, lsum[mt][0], 2);
        lsum[mt][1] += __shfl_xor_sync(0xffffffffu, lsum[mt][1], 1);
        lsum[mt][1] += __shfl_xor_sync(0xffffffffu, lsum[mt][1], 2);
    }

    int bb = bh >> 4, h = bh & 15;
#pragma unroll
    for (int mt = 0; mt < 2; mt++) {
        float inv0 = 1.0f / lsum[mt][0], inv1 = 1.0f / lsum[mt][1];
        int row0 = bb * L_ + qt * 128 + w * 32 + mt * 16 + (lane >> 2);
#pragma unroll
        for (int nt = 0; nt < 8; nt++) {
            int d = h * HD_ + nt * 8 + 2 * (lane & 3);
            *reinterpret_cast<uint*>(&g_ctxb[(size_t)row0 * D_ + d]) =
                packbf2(o[mt][nt][0] * inv0, o[mt][nt][1] * inv0);
            *reinterpret_cast<uint*>(&g_ctxb[(size_t)(row0 + 8) * D_ + d]) =
                packbf2(o[mt][nt][2] * inv1, o[mt][nt][3] * inv1);
        }
    }
}

// ---------------------------------------------------------------------------
// Kernel 4: LayerNorm -> d_out
// ---------------------------------------------------------------------------
__global__ void __launch_bounds__(256)
ln_kernel(const float* __restrict__ gamma, const float* __restrict__ beta,
          float* __restrict__ out) {
    int row = blockIdx.x, tid = threadIdx.x;
    const float4 v = *reinterpret_cast<const float4*>(&g_Y[(size_t)row * D_ + tid * 4]);
    float s = v.x + v.y + v.z + v.w;
    float q = v.x * v.x + v.y * v.y + v.z * v.z + v.w * v.w;

    __shared__ float sb[2][8];
#pragma unroll
    for (int o = 16; o >= 1; o >>= 1) {
        s += __shfl_xor_sync(0xffffffffu, s, o);
        q += __shfl_xor_sync(0xffffffffu, q, o);
    }
    if ((tid & 31) == 0) { sb[0][tid >> 5] = s; sb[1][tid >> 5] = q; }
    __syncthreads();
    s = 0.f; q = 0.f;
#pragma unroll
    for (int w = 0; w < 8; w++) { s += sb[0][w]; q += sb[1][w]; }

    float mu   = s * (1.0f / D_);
    float var  = q * (1.0f / D_) - mu * mu;
    float rstd = rsqrtf(var + EPS);

    const float4 g  = *reinterpret_cast<const float4*>(&gamma[tid * 4]);
    const float4 be = *reinterpret_cast<const float4*>(&beta[tid * 4]);
    float4 o4;
    o4.x = (v.x - mu) * rstd * g.x + be.x;
    o4.y = (v.y - mu) * rstd * g.y + be.y;
    o4.z = (v.z - mu) * rstd * g.z + be.z;
    o4.w = (v.w - mu) * rstd * g.w + be.w;
    *reinterpret_cast<float4*>(&out[(size_t)row * D_ + tid * 4]) = o4;
}

// ---------------------------------------------------------------------------
extern "C" void kernel_launch(void* const* d_in, const int* in_sizes, int n_in,
                              void* d_out, int out_size) {
    const float* x     = (const float*)d_in[0];
    const float* Wq    = (const float*)d_in[1];
    const float* bq    = (const float*)d_in[2];
    const float* Wk    = (const float*)d_in[3];
    const float* bk    = (const float*)d_in[4];
    const float* Wv    = (const float*)d_in[5];
    const float* bv    = (const float*)d_in[6];
    const float* Wo    = (const float*)d_in[7];
    const float* bo    = (const float*)d_in[8];
    const float* gamma = (const float*)d_in[9];
    const float* beta  = (const float*)d_in[10];
    float* out = (float*)d_out;

    cudaFuncSetAttribute(qkv_kernel,
                         cudaFuncAttributeMaxDynamicSharedMemorySize, G_SMEM);
    cudaFuncSetAttribute(oproj_kernel,
                         cudaFuncAttributeMaxDynamicSharedMemorySize, G_SMEM);

    cvt_all_kernel<<<8192, 256>>>(x, Wq, Wk, Wv, Wo);

    dim3 g1(8, 64, 3);
    qkv_kernel<<<g1, 128, G_SMEM>>>(bq, bk, bv);

    dim3 g2(L_ / 128, B_ * H_);
    attn_kernel<<<g2, 128>>>();

    dim3 g3(8, 64);
    oproj_kernel<<<g3, 128, G_SMEM>>>(bo, x);

    ln_kernel<<<M_, 256>>>(gamma, beta, out);
}

// round 16
// speedup vs baseline: 1.0156x; 1.0156x over previous
#include <cuda_runtime.h>
#include <cuda_bf16.h>

#define B_  4
#define L_  2048
#define D_  1024
#define H_  16
#define HD_ 64
#define M_  (B_*L_)
#define EPS 1e-5f
// 0.125 * log2(e), folded into Q projection output
#define QSCALE 0.1803368801111244f

typedef unsigned uint;

// Scratch (device globals; 16B aligned)
__device__ __align__(16) __nv_bfloat16 g_xb[(size_t)M_*D_];
__device__ __align__(16) __nv_bfloat16 g_WbT[4][(size_t)D_*D_];   // W^T: [n][k]
__device__ __align__(16) __nv_bfloat16 g_Qb[(size_t)B_*H_*L_*HD_];
__device__ __align__(16) __nv_bfloat16 g_Kb[(size_t)B_*H_*L_*HD_];
__device__ __align__(16) __nv_bfloat16 g_Vb[(size_t)B_*H_*L_*HD_];
__device__ __align__(16) __nv_bfloat16 g_ctxb[(size_t)M_*D_];
__device__ __align__(16) float g_Y[(size_t)M_*D_];

// ---------------------------------------------------------------------------
// PTX helpers
// ---------------------------------------------------------------------------
__device__ __forceinline__ uint smem_u32(const void* p) {
    return (uint)__cvta_generic_to_shared(p);
}
__device__ __forceinline__ void cpasync16(uint dst, const void* src) {
    asm volatile("cp.async.cg.shared.global [%0], [%1], 16;\n" :: "r"(dst), "l"(src));
}
__device__ __forceinline__ void cp_commit() { asm volatile("cp.async.commit_group;\n"); }
template<int N> __device__ __forceinline__ void cp_wait() {
    asm volatile("cp.async.wait_group %0;\n" :: "n"(N));
}
__device__ __forceinline__ uint packbf2(float lo, float hi) {
    uint r;
    asm("cvt.rn.bf16x2.f32 %0, %1, %2;" : "=r"(r) : "f"(hi), "f"(lo));
    return r;
}
__device__ __forceinline__ float ex2f(float x) {
    float r;
    asm("ex2.approx.f32 %0, %1;" : "=f"(r) : "f"(x));
    return r;
}
__device__ __forceinline__ void ldm4(uint& r0, uint& r1, uint& r2, uint& r3, uint a) {
    asm volatile("ldmatrix.sync.aligned.m8n8.x4.shared.b16 {%0,%1,%2,%3}, [%4];"
                 : "=r"(r0), "=r"(r1), "=r"(r2), "=r"(r3) : "r"(a));
}
__device__ __forceinline__ void ldm4t(uint& r0, uint& r1, uint& r2, uint& r3, uint a) {
    asm volatile("ldmatrix.sync.aligned.m8n8.x4.trans.shared.b16 {%0,%1,%2,%3}, [%4];"
                 : "=r"(r0), "=r"(r1), "=r"(r2), "=r"(r3) : "r"(a));
}
__device__ __forceinline__ void mma16(float* c, const uint* a, uint b0, uint b1) {
    asm volatile(
        "mma.sync.aligned.m16n8k16.row.col.f32.bf16.bf16.f32 "
        "{%0,%1,%2,%3}, {%4,%5,%6,%7}, {%8,%9}, {%0,%1,%2,%3};\n"
        : "+f"(c[0]), "+f"(c[1]), "+f"(c[2]), "+f"(c[3])
        : "r"(a[0]), "r"(a[1]), "r"(a[2]), "r"(a[3]), "r"(b0), "r"(b1));
}

// ---------------------------------------------------------------------------
// Merged conversion kernel: blocks [0,4096) convert x; [4096,8192) transpose W.
// ---------------------------------------------------------------------------
__global__ void __launch_bounds__(256)
cvt_all_kernel(const float* __restrict__ x,
               const float* __restrict__ Wq, const float* __restrict__ Wk,
               const float* __restrict__ Wv, const float* __restrict__ Wo) {
    int b = blockIdx.x;
    if (b < 4096) {
        int i = b * 256 + threadIdx.x;
        const float4* sp = reinterpret_cast<const float4*>(x) + (size_t)i * 2;
        float4 a = sp[0], c = sp[1];
        uint4 o;
        o.x = packbf2(a.x, a.y); o.y = packbf2(a.z, a.w);
        o.z = packbf2(c.x, c.y); o.w = packbf2(c.z, c.w);
        reinterpret_cast<uint4*>(g_xb)[i] = o;
    } else {
        __shared__ float t[32][33];
        int wb = b - 4096;
        int z = wb >> 10;
        int tile = wb & 1023;
        int k0 = (tile & 31) * 32, n0 = (tile >> 5) * 32;
        const float* src = (z == 0) ? Wq : (z == 1) ? Wk : (z == 2) ? Wv : Wo;
        int tx = threadIdx.x & 31, ty = threadIdx.x >> 5;
#pragma unroll
        for (int i = 0; i < 4; i++)
            t[ty + 8 * i][tx] = src[(size_t)(k0 + ty + 8 * i) * D_ + n0 + tx];
        __syncthreads();
        __nv_bfloat16* dst = g_WbT[z];
#pragma unroll
        for (int i = 0; i < 4; i++)
            dst[(size_t)(n0 + ty + 8 * i) * D_ + k0 + tx] =
                __float2bfloat16(t[tx][ty + 8 * i]);
    }
}

// ---------------------------------------------------------------------------
// Shared GEMM constants: CTA tile 128x128, BK=64, 3-stage cp.async.
// Rows padded to 72 halves = 144B (conflict-free ldmatrix phases).
// ---------------------------------------------------------------------------
#define GKR 72
#define G_ASTG (128*GKR*2)          // 18432 B
#define G_BSTG (128*GKR*2)          // 18432 B
#define G_STG  (G_ASTG + G_BSTG)    // 36864 B
#define G_SMEM (3*G_STG)            // 110592 B

// --- 256-thread issue (R12/R14 qkv variant) ---
__device__ __forceinline__ void g_issue256(const __nv_bfloat16* __restrict__ A,
                                           const __nv_bfloat16* __restrict__ Bt,
                                           int bm, int bn, int k0, uint sbase) {
    int tid = threadIdx.x;
#pragma unroll
    for (int i = 0; i < 4; i++) {
        int c = tid + i * 256;
        int r = c >> 3, kc = (c & 7) * 8;
        cpasync16(sbase + (uint)(r * GKR + kc) * 2,
                  A + (size_t)(bm + r) * D_ + k0 + kc);
    }
#pragma unroll
    for (int i = 0; i < 4; i++) {
        int c = tid + i * 256;
        int r = c >> 3, kc = (c & 7) * 8;
        cpasync16(sbase + G_ASTG + (uint)(r * GKR + kc) * 2,
                  Bt + (size_t)(bn + r) * D_ + k0 + kc);
    }
}

// --- 128-thread issue (R15 oproj variant) ---
__device__ __forceinline__ void g_issue128(const __nv_bfloat16* __restrict__ A,
                                           const __nv_bfloat16* __restrict__ Bt,
                                           int bm, int bn, int k0, uint sbase) {
    int tid = threadIdx.x;
#pragma unroll
    for (int i = 0; i < 8; i++) {
        int c = tid + i * 128;
        int r = c >> 3, kc = (c & 7) * 8;
        cpasync16(sbase + (uint)(r * GKR + kc) * 2,
                  A + (size_t)(bm + r) * D_ + k0 + kc);
    }
#pragma unroll
    for (int i = 0; i < 8; i++) {
        int c = tid + i * 128;
        int r = c >> 3, kc = (c & 7) * 8;
        cpasync16(sbase + G_ASTG + (uint)(r * GKR + kc) * 2,
                  Bt + (size_t)(bn + r) * D_ + k0 + kc);
    }
}

// --- warp 32x64 compute (8 warps 4x2; qkv) ---
__device__ __forceinline__ void g_compute32(uint sA, uint sB, int lane,
                                            int wm, int wn, float acc[2][8][4]) {
    int ra = lane & 15;
    int ca0 = (lane & 16) ? 8 : 0;
    int rb = (lane & 7) + ((lane & 16) ? 8 : 0);
#pragma unroll
    for (int ks = 0; ks < 4; ks++) {
        uint a[2][4];
#pragma unroll
        for (int mt = 0; mt < 2; mt++) {
            int r = wm * 32 + mt * 16 + ra;
            ldm4(a[mt][0], a[mt][1], a[mt][2], a[mt][3],
                 sA + (uint)(r * GKR + ks * 16 + ca0) * 2);
        }
        int cb = ks * 16 + ((lane & 8) ? 8 : 0);
#pragma unroll
        for (int np = 0; np < 4; np++) {
            int n = wn * 64 + np * 16 + rb;
            uint b0, b1, b2, b3;
            ldm4(b0, b1, b2, b3, sB + (uint)(n * GKR + cb) * 2);
#pragma unroll
            for (int mt = 0; mt < 2; mt++) {
                mma16(acc[mt][np * 2],     a[mt], b0, b1);
                mma16(acc[mt][np * 2 + 1], a[mt], b2, b3);
            }
        }
    }
}

// --- warp 64x64 compute (4 warps 2x2; oproj) ---
__device__ __forceinline__ void g_compute64(uint sA, uint sB, int lane,
                                            int wm, int wn, float acc[4][8][4]) {
    int ra = lane & 15;
    int ca0 = (lane & 16) ? 8 : 0;
    int rb = (lane & 7) + ((lane & 16) ? 8 : 0);
#pragma unroll
    for (int ks = 0; ks < 4; ks++) {
        uint a[4][4];
#pragma unroll
        for (int mt = 0; mt < 4; mt++) {
            int r = wm * 64 + mt * 16 + ra;
            ldm4(a[mt][0], a[mt][1], a[mt][2], a[mt][3],
                 sA + (uint)(r * GKR + ks * 16 + ca0) * 2);
        }
        int cb = ks * 16 + ((lane & 8) ? 8 : 0);
#pragma unroll
        for (int np = 0; np < 4; np++) {
            int n = wn * 64 + np * 16 + rb;
            uint b0, b1, b2, b3;
            ldm4(b0, b1, b2, b3, sB + (uint)(n * GKR + cb) * 2);
#pragma unroll
            for (int mt = 0; mt < 4; mt++) {
                mma16(acc[mt][np * 2],     a[mt], b0, b1);
                mma16(acc[mt][np * 2 + 1], a[mt], b2, b3);
            }
        }
    }
}

// ---------------------------------------------------------------------------
// Kernel 1: QKV projection -> bf16 [B,H,L,HD]; grid (8, 64, 3), 256 threads
// (R12/R14 GEMM variant: warp 32x64, 2 CTAs/SM, 16 warps/SM)
// ---------------------------------------------------------------------------
__global__ void __launch_bounds__(256, 2)
qkv_kernel(const float* __restrict__ bq, const float* __restrict__ bk,
           const float* __restrict__ bv) {
    extern __shared__ __align__(16) __nv_bfloat16 dsm[];
    uint sb = smem_u32(dsm);
    int z = blockIdx.z;
    int bm = blockIdx.y * 128, bn = blockIdx.x * 128;
    const float* bias = (z == 0) ? bq : (z == 1) ? bk : bv;
    __nv_bfloat16* out = (z == 0) ? g_Qb : (z == 1) ? g_Kb : g_Vb;
    const float scale = (z == 0) ? QSCALE : 1.0f;
    const __nv_bfloat16* A = g_xb;
    const __nv_bfloat16* Bt = g_WbT[z];

    float acc[2][8][4];
#pragma unroll
    for (int mt = 0; mt < 2; mt++)
#pragma unroll
        for (int nt = 0; nt < 8; nt++)
#pragma unroll
            for (int j = 0; j < 4; j++) acc[mt][nt][j] = 0.f;

    int lane = threadIdx.x & 31, w = threadIdx.x >> 5;
    int wm = w & 3, wn = w >> 2;

    g_issue256(A, Bt, bm, bn, 0, sb);
    cp_commit();
    g_issue256(A, Bt, bm, bn, 64, sb + G_STG);
    cp_commit();

    for (int it = 0; it < 16; it++) {
        if (it + 1 < 16) cp_wait<1>(); else cp_wait<0>();
        __syncthreads();
        uint base = sb + (uint)(it % 3) * G_STG;
        g_compute32(base, base + G_ASTG, lane, wm, wn, acc);
        if (it + 2 < 16) {
            uint nbase = sb + (uint)((it + 2) % 3) * G_STG;
            g_issue256(A, Bt, bm, bn, (it + 2) * 64, nbase);
            cp_commit();
        }
    }

#pragma unroll
    for (int mt = 0; mt < 2; mt++) {
        int r0 = bm + wm * 32 + mt * 16 + (lane >> 2);
#pragma unroll
        for (int nt = 0; nt < 8; nt++) {
            int c0 = bn + wn * 64 + nt * 8 + 2 * (lane & 3);
            int h = c0 >> 6, d = c0 & 63;
            float bx = bias[c0], by = bias[c0 + 1];
#pragma unroll
            for (int rr = 0; rr < 2; rr++) {
                int r = r0 + rr * 8;
                int bb = r >> 11, ll = r & (L_ - 1);
                uint p = packbf2((acc[mt][nt][rr * 2]     + bx) * scale,
                                 (acc[mt][nt][rr * 2 + 1] + by) * scale);
                *reinterpret_cast<uint*>(
                    &out[(((size_t)(bb * H_ + h)) * L_ + ll) * HD_ + d]) = p;
            }
        }
    }
}

// ---------------------------------------------------------------------------
// Kernel 3: output projection + bias + residual -> g_Y fp32; grid (8, 64),
// 128 threads (R15 GEMM variant: warp 64x64 — measured faster at this scale)
// ---------------------------------------------------------------------------
__global__ void __launch_bounds__(128, 2)
oproj_kernel(const float* __restrict__ bo, const float* __restrict__ x) {
    extern __shared__ __align__(16) __nv_bfloat16 dsm[];
    uint sb = smem_u32(dsm);
    int bm = blockIdx.y * 128, bn = blockIdx.x * 128;
    const __nv_bfloat16* A = g_ctxb;
    const __nv_bfloat16* Bt = g_WbT[3];

    float acc[4][8][4];
#pragma unroll
    for (int mt = 0; mt < 4; mt++)
#pragma unroll
        for (int nt = 0; nt < 8; nt++)
#pragma unroll
            for (int j = 0; j < 4; j++) acc[mt][nt][j] = 0.f;

    int lane = threadIdx.x & 31, w = threadIdx.x >> 5;
    int wm = w & 1, wn = w >> 1;

    g_issue128(A, Bt, bm, bn, 0, sb);
    cp_commit();
    g_issue128(A, Bt, bm, bn, 64, sb + G_STG);
    cp_commit();

    for (int it = 0; it < 16; it++) {
        if (it + 1 < 16) cp_wait<1>(); else cp_wait<0>();
        __syncthreads();
        uint base = sb + (uint)(it % 3) * G_STG;
        g_compute64(base, base + G_ASTG, lane, wm, wn, acc);
        if (it + 2 < 16) {
            uint nbase = sb + (uint)((it + 2) % 3) * G_STG;
            g_issue128(A, Bt, bm, bn, (it + 2) * 64, nbase);
            cp_commit();
        }
    }

#pragma unroll
    for (int mt = 0; mt < 4; mt++) {
        int r0 = bm + wm * 64 + mt * 16 + (lane >> 2);
#pragma unroll
        for (int nt = 0; nt < 8; nt++) {
            int c0 = bn + wn * 64 + nt * 8 + 2 * (lane & 3);
            float bx = bo[c0], by = bo[c0 + 1];
#pragma unroll
            for (int rr = 0; rr < 2; rr++) {
                int r = r0 + rr * 8;
                const float2 xr = *reinterpret_cast<const float2*>(&x[(size_t)r * D_ + c0]);
                float2 v;
                v.x = acc[mt][nt][rr * 2]     + bx + xr.x;
                v.y = acc[mt][nt][rr * 2 + 1] + by + xr.y;
                *reinterpret_cast<float2*>(&g_Y[(size_t)r * D_ + c0]) = v;
            }
        }
    }
}

// ---------------------------------------------------------------------------
// Kernel 2: Flash attention (exact R14 form — measured best). 128 threads,
// 4 warps, 128-q tile, each warp 32 q-rows (K/V fragments shared 2 m-tiles).
// ---------------------------------------------------------------------------
#define QST 72
#define KVSTG (2 * 64 * QST)     // halves per stage

__device__ __forceinline__ void attn_issue_kv(const __nv_bfloat16* __restrict__ Kp,
                                              const __nv_bfloat16* __restrict__ Vp,
                                              int t, uint kb, uint vb, int tid) {
#pragma unroll
    for (int i = 0; i < 4; i++) {
        int idx = tid + i * 128;
        int r = idx >> 3, c = (idx & 7) * 8;
        size_t g = (size_t)(t * 64 + r) * HD_ + c;
        cpasync16(kb + (uint)(r * QST + c) * 2, Kp + g);
        cpasync16(vb + (uint)(r * QST + c) * 2, Vp + g);
    }
}

__global__ void __launch_bounds__(128, 2)
attn_kernel() {
    __shared__ __align__(16) __nv_bfloat16 KV[2][KVSTG];   // 36864 B

    int tid = threadIdx.x, lane = tid & 31, w = tid >> 5;   // w in 0..3
    int qt = blockIdx.x, bh = blockIdx.y;
    const __nv_bfloat16* Qp = g_Qb + (size_t)bh * L_ * HD_ + (size_t)qt * 128 * HD_;
    const __nv_bfloat16* Kp = g_Kb + (size_t)bh * L_ * HD_;
    const __nv_bfloat16* Vp = g_Vb + (size_t)bh * L_ * HD_;

    uint kb[2] = { smem_u32(&KV[0][0]), smem_u32(&KV[1][0]) };
    uint vb[2] = { kb[0] + 64 * QST * 2, kb[1] + 64 * QST * 2 };
    uint qb = kb[0];

    // Stage Q (128 x 64, stride QST) into stage-0
#pragma unroll
    for (int i = 0; i < 8; i++) {
        int idx = tid + i * 128;
        int r = idx >> 3, c = (idx & 7) * 8;
        cpasync16(qb + (uint)(r * QST + c) * 2, Qp + (size_t)r * HD_ + c);
    }
    cp_commit();
    cp_wait<0>();
    __syncthreads();

    // Preload Q fragments: 2 m-tiles x 4 k-steps
    uint qf[2][4][4];
    {
        int koff = (lane >> 4) ? 8 : 0;
#pragma unroll
        for (int mt = 0; mt < 2; mt++) {
            int m = w * 32 + mt * 16 + (lane & 15);
#pragma unroll
            for (int ks = 0; ks < 4; ks++)
                ldm4(qf[mt][ks][0], qf[mt][ks][1], qf[mt][ks][2], qf[mt][ks][3],
                     qb + (uint)(m * QST + ks * 16 + koff) * 2);
        }
    }
    __syncthreads();

    attn_issue_kv(Kp, Vp, 0, kb[0], vb[0], tid);
    cp_commit();
    attn_issue_kv(Kp, Vp, 1, kb[1], vb[1], tid);
    cp_commit();

    float o[2][8][4];
#pragma unroll
    for (int mt = 0; mt < 2; mt++)
#pragma unroll
        for (int nt = 0; nt < 8; nt++)
#pragma unroll
            for (int j = 0; j < 4; j++) o[mt][nt][j] = 0.f;
    float lsum[2][2] = {{0.f, 0.f}, {0.f, 0.f}};

    int row = lane & 7, grp = lane >> 3;

    for (int t = 0; t < L_ / 64; t++) {
        if (t + 2 < L_ / 64) cp_wait<1>(); else cp_wait<0>();
        __syncthreads();
        uint kcur = kb[t & 1], vcur = vb[t & 1];

        // ---- S = Q @ K^T : K fragments shared across both m-tiles ----
        float s[2][8][4];
#pragma unroll
        for (int mt = 0; mt < 2; mt++)
#pragma unroll
            for (int nt = 0; nt < 8; nt++)
#pragma unroll
                for (int j = 0; j < 4; j++) s[mt][nt][j] = 0.f;
#pragma unroll
        for (int ks = 0; ks < 4; ks++) {
            int kk = ks * 16 + ((grp & 1) ? 8 : 0);
#pragma unroll
            for (int np = 0; np < 4; np++) {
                int nn = np * 16 + ((grp >= 2) ? 8 : 0) + row;
                uint b0, b1, b2, b3;
                ldm4(b0, b1, b2, b3, kcur + (uint)(nn * QST + kk) * 2);
#pragma unroll
                for (int mt = 0; mt < 2; mt++) {
                    mma16(s[mt][np * 2],     qf[mt][ks], b0, b1);
                    mma16(s[mt][np * 2 + 1], qf[mt][ks], b2, b3);
                }
            }
        }

        // ---- P = 2^S; partial row sums ----
#pragma unroll
        for (int mt = 0; mt < 2; mt++)
#pragma unroll
            for (int nt = 0; nt < 8; nt++) {
                s[mt][nt][0] = ex2f(s[mt][nt][0]);
                s[mt][nt][1] = ex2f(s[mt][nt][1]);
                s[mt][nt][2] = ex2f(s[mt][nt][2]);
                s[mt][nt][3] = ex2f(s[mt][nt][3]);
                lsum[mt][0] += s[mt][nt][0] + s[mt][nt][1];
                lsum[mt][1] += s[mt][nt][2] + s[mt][nt][3];
            }

        // ---- O += P @ V : V fragments shared across both m-tiles ----
#pragma unroll
        for (int kt = 0; kt < 4; kt++) {
            uint a[2][4];
#pragma unroll
            for (int mt = 0; mt < 2; mt++) {
                a[mt][0] = packbf2(s[mt][2 * kt][0],     s[mt][2 * kt][1]);
                a[mt][1] = packbf2(s[mt][2 * kt][2],     s[mt][2 * kt][3]);
                a[mt][2] = packbf2(s[mt][2 * kt + 1][0], s[mt][2 * kt + 1][1]);
                a[mt][3] = packbf2(s[mt][2 * kt + 1][2], s[mt][2 * kt + 1][3]);
            }
            int kk = kt * 16 + ((grp & 1) ? 8 : 0) + row;
#pragma unroll
            for (int np = 0; np < 4; np++) {
                int nn = np * 16 + ((grp >= 2) ? 8 : 0);
                uint b0, b1, b2, b3;
                ldm4t(b0, b1, b2, b3, vcur + (uint)(kk * QST + nn) * 2);
#pragma unroll
                for (int mt = 0; mt < 2; mt++) {
                    mma16(o[mt][np * 2],     a[mt], b0, b1);
                    mma16(o[mt][np * 2 + 1], a[mt], b2, b3);
                }
            }
        }
        __syncthreads();
        if (t + 2 < L_ / 64) {
            attn_issue_kv(Kp, Vp, t + 2, kb[t & 1], vb[t & 1], tid);
            cp_commit();
        }
    }

    // Row-sum reduction across the 4-lane row groups
#pragma unroll
    for (int mt = 0; mt < 2; mt++) {
        lsum[mt][0] += __shfl_xor_sync(0xffffffffu, lsum[mt][0], 1);
        lsum[mt][0] += __shfl_xor_sync(0xffffffffu, lsum[mt][0], 2);
        lsum[mt][1] += __shfl_xor_sync(0xffffffffu, lsum[mt][1], 1);
        lsum[mt][1] += __shfl_xor_sync(0xffffffffu, lsum[mt][1], 2);
    }

    int bb = bh >> 4, h = bh & 15;
#pragma unroll
    for (int mt = 0; mt < 2; mt++) {
        float inv0 = 1.0f / lsum[mt][0], inv1 = 1.0f / lsum[mt][1];
        int row0 = bb * L_ + qt * 128 + w * 32 + mt * 16 + (lane >> 2);
#pragma unroll
        for (int nt = 0; nt < 8; nt++) {
            int d = h * HD_ + nt * 8 + 2 * (lane & 3);
            *reinterpret_cast<uint*>(&g_ctxb[(size_t)row0 * D_ + d]) =
                packbf2(o[mt][nt][0] * inv0, o[mt][nt][1] * inv0);
            *reinterpret_cast<uint*>(&g_ctxb[(size_t)(row0 + 8) * D_ + d]) =
                packbf2(o[mt][nt][2] * inv1, o[mt][nt][3] * inv1);
        }
    }
}

// ---------------------------------------------------------------------------
// Kernel 4: LayerNorm -> d_out
// ---------------------------------------------------------------------------
__global__ void __launch_bounds__(256)
ln_kernel(const float* __restrict__ gamma, const float* __restrict__ beta,
          float* __restrict__ out) {
    int row = blockIdx.x, tid = threadIdx.x;
    const float4 v = *reinterpret_cast<const float4*>(&g_Y[(size_t)row * D_ + tid * 4]);
    float s = v.x + v.y + v.z + v.w;
    float q = v.x * v.x + v.y * v.y + v.z * v.z + v.w * v.w;

    __shared__ float sb[2][8];
#pragma unroll
    for (int o = 16; o >= 1; o >>= 1) {
        s += __shfl_xor_sync(0xffffffffu, s, o);
        q += __shfl_xor_sync(0xffffffffu, q, o);
    }
    if ((tid & 31) == 0) { sb[0][tid >> 5] = s; sb[1][tid >> 5] = q; }
    __syncthreads();
    s = 0.f; q = 0.f;
#pragma unroll
    for (int w = 0; w < 8; w++) { s += sb[0][w]; q += sb[1][w]; }

    float mu   = s * (1.0f / D_);
    float var  = q * (1.0f / D_) - mu * mu;
    float rstd = rsqrtf(var + EPS);

    const float4 g  = *reinterpret_cast<const float4*>(&gamma[tid * 4]);
    const float4 be = *reinterpret_cast<const float4*>(&beta[tid * 4]);
    float4 o4;
    o4.x = (v.x - mu) * rstd * g.x + be.x;
    o4.y = (v.y - mu) * rstd * g.y + be.y;
    o4.z = (v.z - mu) * rstd * g.z + be.z;
    o4.w = (v.w - mu) * rstd * g.w + be.w;
    *reinterpret_cast<float4*>(&out[(size_t)row * D_ + tid * 4]) = o4;
}

// ---------------------------------------------------------------------------
extern "C" void kernel_launch(void* const* d_in, const int* in_sizes, int n_in,
                              void* d_out, int out_size) {
    const float* x     = (const float*)d_in[0];
    const float* Wq    = (const float*)d_in[1];
    const float* bq    = (const float*)d_in[2];
    const float* Wk    = (const float*)d_in[3];
    const float* bk    = (const float*)d_in[4];
    const float* Wv    = (const float*)d_in[5];
    const float* bv    = (const float*)d_in[6];
    const float* Wo    = (const float*)d_in[7];
    const float* bo    = (const float*)d_in[8];
    const float* gamma = (const float*)d_in[9];
    const float* beta  = (const float*)d_in[10];
    float* out = (float*)d_out;

    cudaFuncSetAttribute(qkv_kernel,
                         cudaFuncAttributeMaxDynamicSharedMemorySize, G_SMEM);
    cudaFuncSetAttribute(oproj_kernel,
                         cudaFuncAttributeMaxDynamicSharedMemorySize, G_SMEM);

    cvt_all_kernel<<<8192, 256>>>(x, Wq, Wk, Wv, Wo);

    dim3 g1(8, 64, 3);
    qkv_kernel<<<g1, 256, G_SMEM>>>(bq, bk, bv);

    dim3 g2(L_ / 128, B_ * H_);
    attn_kernel<<<g2, 128>>>();

    dim3 g3(8, 64);
    oproj_kernel<<<g3, 128, G_SMEM>>>(bo, x);

    ln_kernel<<<M_, 256>>>(gamma, beta, out);
}